// round 7
// baseline (speedup 1.0000x reference)
#include <cuda_runtime.h>
#include <math.h>

#define B_   2
#define T_   2048
#define NH   32
#define NG   8
#define HD   64
#define DM   2048     // D_MODEL
#define KVD  512      // NG*HD
#define QKVN 3072     // DM + 2*KVD

// ---------------- scratch (device globals: allocation-free) ----------------
__device__ float g_qkv[(size_t)B_ * T_ * QKVN];      // [4096, 3072]
__device__ float g_q  [(size_t)B_ * NH * T_ * HD];   // [B,H,T,D] roped
__device__ float g_k  [(size_t)B_ * NG * T_ * HD];   // [B,G,T,D] roped
__device__ float g_v  [(size_t)B_ * NG * T_ * HD];   // [B,G,T,D]
__device__ float g_y  [(size_t)B_ * T_ * DM];        // attention out, [B,T,C]

// ---------------- fp32 tiled GEMM: C[M,N] = A[M,K] @ B[K,N] ----------------
// BM=BN=128, BK=16, 256 threads, 8x8 per thread. All dims divisible.
__global__ __launch_bounds__(256) void sgemm_kernel(
    const float* __restrict__ A, const float* __restrict__ B,
    float* __restrict__ C, int M, int N, int K)
{
    __shared__ float As[16][128];   // transposed A tile
    __shared__ float Bs[16][128];

    const int tid = threadIdx.x;
    const int brow = blockIdx.y, bcol = blockIdx.x;

    const float* Ab = A + (size_t)brow * 128 * K;
    const float* Bb = B + (size_t)bcol * 128;

    const int tr = tid >> 4;       // 0..15
    const int tc = tid & 15;       // 0..15

    const int a_row  = tid >> 2;   // 0..63 (+64)
    const int a_col4 = tid & 3;    // float4 index in 16-wide row
    const int b_row  = tid >> 5;   // 0..7  (+8)
    const int b_col4 = tid & 31;   // float4 col

    float acc[8][8];
    #pragma unroll
    for (int i = 0; i < 8; i++)
        #pragma unroll
        for (int j = 0; j < 8; j++) acc[i][j] = 0.f;

    for (int k0 = 0; k0 < K; k0 += 16) {
        #pragma unroll
        for (int p = 0; p < 2; p++) {
            int r = a_row + p * 64;
            float4 v = *(const float4*)(Ab + (size_t)r * K + k0 + a_col4 * 4);
            As[a_col4 * 4 + 0][r] = v.x;
            As[a_col4 * 4 + 1][r] = v.y;
            As[a_col4 * 4 + 2][r] = v.z;
            As[a_col4 * 4 + 3][r] = v.w;
        }
        #pragma unroll
        for (int p = 0; p < 2; p++) {
            int r = b_row + p * 8;
            *(float4*)(&Bs[r][b_col4 * 4]) =
                *(const float4*)(Bb + (size_t)(k0 + r) * N + b_col4 * 4);
        }
        __syncthreads();

        #pragma unroll
        for (int kk = 0; kk < 16; kk++) {
            float a[8], b[8];
            *(float4*)(a)     = *(const float4*)(&As[kk][tr * 8]);
            *(float4*)(a + 4) = *(const float4*)(&As[kk][tr * 8 + 4]);
            *(float4*)(b)     = *(const float4*)(&Bs[kk][tc * 8]);
            *(float4*)(b + 4) = *(const float4*)(&Bs[kk][tc * 8 + 4]);
            #pragma unroll
            for (int i = 0; i < 8; i++)
                #pragma unroll
                for (int j = 0; j < 8; j++)
                    acc[i][j] = fmaf(a[i], b[j], acc[i][j]);
        }
        __syncthreads();
    }

    float* Cb = C + (size_t)brow * 128 * N + bcol * 128;
    #pragma unroll
    for (int i = 0; i < 8; i++) {
        float4 o0 = make_float4(acc[i][0], acc[i][1], acc[i][2], acc[i][3]);
        float4 o1 = make_float4(acc[i][4], acc[i][5], acc[i][6], acc[i][7]);
        float* row = Cb + (size_t)(tr * 8 + i) * N + tc * 8;
        *(float4*)(row)     = o0;
        *(float4*)(row + 4) = o1;
    }
}

// ---------------- RoPE + scatter into attention-friendly layouts ----------
// q pairs: B*T*NH*32 ; k pairs: B*T*NG*32 ; v pairs: B*T*NG*32 (copy only)
#define QP_ (B_ * T_ * NH * 32)   // 4194304
#define KP_ (B_ * T_ * NG * 32)   // 1048576

__global__ __launch_bounds__(256) void rope_prepare_kernel()
{
    int id = blockIdx.x * blockDim.x + threadIdx.x;
    if (id < QP_) {
        int i = id & 31;
        int h = (id >> 5) & 31;
        int t = (id >> 10) & 2047;
        int b = id >> 21;
        const float* src = g_qkv + ((size_t)(b * T_ + t)) * QKVN + h * 64 + 2 * i;
        float x0 = src[0], x1 = src[1];
        float inv = powf(10000.0f, -(float)(2 * i) / 64.0f);
        float sn, cs;
        sincosf((float)t * inv, &sn, &cs);
        float* dst = g_q + (((size_t)(b * NH + h)) * T_ + t) * HD + 2 * i;
        dst[0] = x0 * cs - x1 * sn;
        dst[1] = x0 * sn + x1 * cs;
    } else if (id < QP_ + KP_) {
        int id2 = id - QP_;
        int i = id2 & 31;
        int g = (id2 >> 5) & 7;
        int t = (id2 >> 8) & 2047;
        int b = id2 >> 19;
        const float* src = g_qkv + ((size_t)(b * T_ + t)) * QKVN + DM + g * 64 + 2 * i;
        float x0 = src[0], x1 = src[1];
        float inv = powf(10000.0f, -(float)(2 * i) / 64.0f);
        float sn, cs;
        sincosf((float)t * inv, &sn, &cs);
        float* dst = g_k + (((size_t)(b * NG + g)) * T_ + t) * HD + 2 * i;
        dst[0] = x0 * cs - x1 * sn;
        dst[1] = x0 * sn + x1 * cs;
    } else if (id < QP_ + 2 * KP_) {
        int id2 = id - QP_ - KP_;
        int i = id2 & 31;
        int g = (id2 >> 5) & 7;
        int t = (id2 >> 8) & 2047;
        int b = id2 >> 19;
        const float* src = g_qkv + ((size_t)(b * T_ + t)) * QKVN + DM + KVD + g * 64 + 2 * i;
        float* dst = g_v + (((size_t)(b * NG + g)) * T_ + t) * HD + 2 * i;
        dst[0] = src[0];
        dst[1] = src[1];
    }
}

// ---------------- causal flash attention, 64-row Q tiles -------------------
// grid: (T/64, B*NH), 128 threads. Each thread: 4 q-rows x 8 cols/dims.
// K/V/Q smem tiles: stride 64 with XOR chunk swizzle keyed on (row>>3)&7
// -> conflict-free K reads when 8 lanes read rows {j, j+8, ..., j+56}.
#define ATTN_SMEM ((3 * 64 * 64 + 64 * 68) * 4)   // 66560 bytes

__global__ __launch_bounds__(128) void attn_kernel(
    const float* __restrict__ Q, const float* __restrict__ K,
    const float* __restrict__ V, float* __restrict__ Y)
{
    extern __shared__ float sm[];
    float* Qs = sm;             // 64*64 swizzled
    float* Ks = sm + 4096;      // 64*64 swizzled
    float* Vs = sm + 8192;      // 64*64 swizzled
    float* Ps = sm + 12288;     // 64 rows, stride 68

    const int qt = blockIdx.x;          // 0..31
    const int bh = blockIdx.y;          // 0..63
    const int b = bh >> 5;
    const int h = bh & 31;
    const int g = h >> 2;

    const float* Qp = Q + (((size_t)(b * NH + h)) * T_ + (size_t)qt * 64) * HD;
    const float* Kp = K + (((size_t)(b * NG + g)) * T_) * HD;
    const float* Vp = V + (((size_t)(b * NG + g)) * T_) * HD;

    const int tid = threadIdx.x;

    // load Q tile (swizzled)
    for (int i = tid; i < 1024; i += 128) {
        int r = i >> 4, c = i & 15;
        int sw = c ^ ((r >> 3) & 7);
        *(float4*)(Qs + r * 64 + sw * 4) = *(const float4*)(Qp + r * 64 + c * 4);
    }

    const int r0 = (tid >> 3) << 2;     // 4 q rows
    const int c0 = (tid & 7) << 3;      // 8 k cols / 8 out dims

    float m[4], l[4], acc[4][8];
    #pragma unroll
    for (int i = 0; i < 4; i++) {
        m[i] = -1e30f; l[i] = 0.f;
        #pragma unroll
        for (int j = 0; j < 8; j++) acc[i][j] = 0.f;
    }

    const float scale = 0.125f;   // 1/sqrt(64)

    for (int kt = 0; kt <= qt; kt++) {
        __syncthreads();
        // load K,V tiles (swizzled)
        for (int i = tid; i < 1024; i += 128) {
            int r = i >> 4, c = i & 15;
            int sw = c ^ ((r >> 3) & 7);
            const size_t goff = ((size_t)kt * 64 + r) * 64 + c * 4;
            *(float4*)(Ks + r * 64 + sw * 4) = *(const float4*)(Kp + goff);
            *(float4*)(Vs + r * 64 + sw * 4) = *(const float4*)(Vp + goff);
        }
        __syncthreads();

        // ---- QK^T: s[4][8] ----
        float s[4][8];
        #pragma unroll
        for (int i = 0; i < 4; i++)
            #pragma unroll
            for (int j = 0; j < 8; j++) s[i][j] = 0.f;

        #pragma unroll
        for (int c = 0; c < 16; c++) {
            float4 qf[4], kf[8];
            #pragma unroll
            for (int i = 0; i < 4; i++) {
                int r = r0 + i;
                qf[i] = *(const float4*)(Qs + r * 64 + ((c ^ ((r >> 3) & 7)) << 2));
            }
            #pragma unroll
            for (int j = 0; j < 8; j++) {
                int r = c0 + j;
                kf[j] = *(const float4*)(Ks + r * 64 + ((c ^ ((r >> 3) & 7)) << 2));
            }
            #pragma unroll
            for (int i = 0; i < 4; i++)
                #pragma unroll
                for (int j = 0; j < 8; j++) {
                    s[i][j] = fmaf(qf[i].x, kf[j].x, s[i][j]);
                    s[i][j] = fmaf(qf[i].y, kf[j].y, s[i][j]);
                    s[i][j] = fmaf(qf[i].z, kf[j].z, s[i][j]);
                    s[i][j] = fmaf(qf[i].w, kf[j].w, s[i][j]);
                }
        }

        // ---- online softmax (8 consecutive lanes share each q row) ----
        const bool diag = (kt == qt);
        #pragma unroll
        for (int i = 0; i < 4; i++) {
            #pragma unroll
            for (int j = 0; j < 8; j++) {
                float v = s[i][j] * scale;
                if (diag && (c0 + j) > (r0 + i)) v = -1e30f;
                s[i][j] = v;
            }
            float mt = s[i][0];
            #pragma unroll
            for (int j = 1; j < 8; j++) mt = fmaxf(mt, s[i][j]);
            #pragma unroll
            for (int o = 1; o < 8; o <<= 1)
                mt = fmaxf(mt, __shfl_xor_sync(0xffffffffu, mt, o));
            float mn = fmaxf(m[i], mt);
            float corr = expf(m[i] - mn);
            float lt = 0.f;
            #pragma unroll
            for (int j = 0; j < 8; j++) {
                s[i][j] = expf(s[i][j] - mn);
                lt += s[i][j];
            }
            #pragma unroll
            for (int o = 1; o < 8; o <<= 1)
                lt += __shfl_xor_sync(0xffffffffu, lt, o);
            l[i] = l[i] * corr + lt;
            m[i] = mn;
            #pragma unroll
            for (int j = 0; j < 8; j++) acc[i][j] *= corr;

            float4 p0 = make_float4(s[i][0], s[i][1], s[i][2], s[i][3]);
            float4 p1 = make_float4(s[i][4], s[i][5], s[i][6], s[i][7]);
            *(float4*)(Ps + (r0 + i) * 68 + c0)     = p0;
            *(float4*)(Ps + (r0 + i) * 68 + c0 + 4) = p1;
        }
        __syncthreads();

        // ---- PV: acc += P @ V  (thread dims = c0..c0+7) ----
        const int cq = c0 >> 2;   // even chunk base
        #pragma unroll 8
        for (int k = 0; k < 64; k++) {
            int key = (k >> 3) & 7;
            float4 v0 = *(const float4*)(Vs + k * 64 + ((cq ^ key) << 2));
            float4 v1 = *(const float4*)(Vs + k * 64 + (((cq + 1) ^ key) << 2));
            #pragma unroll
            for (int i = 0; i < 4; i++) {
                float p = Ps[(r0 + i) * 68 + k];
                acc[i][0] = fmaf(p, v0.x, acc[i][0]);
                acc[i][1] = fmaf(p, v0.y, acc[i][1]);
                acc[i][2] = fmaf(p, v0.z, acc[i][2]);
                acc[i][3] = fmaf(p, v0.w, acc[i][3]);
                acc[i][4] = fmaf(p, v1.x, acc[i][4]);
                acc[i][5] = fmaf(p, v1.y, acc[i][5]);
                acc[i][6] = fmaf(p, v1.z, acc[i][6]);
                acc[i][7] = fmaf(p, v1.w, acc[i][7]);
            }
        }
    }

    // epilogue -> g_y in (B,T,C) layout for the proj GEMM
    #pragma unroll
    for (int i = 0; i < 4; i++) {
        float inv = 1.0f / l[i];
        float* dst = Y + ((size_t)(b * T_ + qt * 64 + r0 + i)) * DM + h * 64 + c0;
        float4 o0 = make_float4(acc[i][0] * inv, acc[i][1] * inv,
                                acc[i][2] * inv, acc[i][3] * inv);
        float4 o1 = make_float4(acc[i][4] * inv, acc[i][5] * inv,
                                acc[i][6] * inv, acc[i][7] * inv);
        *(float4*)(dst)     = o0;
        *(float4*)(dst + 4) = o1;
    }
}

// ---------------- launch ---------------------------------------------------
extern "C" void kernel_launch(void* const* d_in, const int* in_sizes, int n_in,
                              void* d_out, int out_size)
{
    const float* x      = (const float*)d_in[0];
    const float* w_qkv  = (const float*)d_in[1];
    const float* w_proj = (const float*)d_in[2];
    float* out = (float*)d_out;

    float *p_qkv, *p_q, *p_k, *p_v, *p_y;
    cudaGetSymbolAddress((void**)&p_qkv, g_qkv);
    cudaGetSymbolAddress((void**)&p_q,   g_q);
    cudaGetSymbolAddress((void**)&p_k,   g_k);
    cudaGetSymbolAddress((void**)&p_v,   g_v);
    cudaGetSymbolAddress((void**)&p_y,   g_y);

    cudaFuncSetAttribute(attn_kernel,
        cudaFuncAttributeMaxDynamicSharedMemorySize, ATTN_SMEM);

    // 1) qkv = x @ w_qkv : [4096,2048] @ [2048,3072]
    sgemm_kernel<<<dim3(QKVN / 128, (B_ * T_) / 128), 256>>>(
        x, w_qkv, p_qkv, B_ * T_, QKVN, DM);

    // 2) RoPE + scatter to [B,H,T,D] / [B,G,T,D]
    {
        int total = QP_ + 2 * KP_;
        rope_prepare_kernel<<<(total + 255) / 256, 256>>>();
    }

    // 3) causal GQA flash attention -> g_y [B,T,C]
    attn_kernel<<<dim3(T_ / 64, B_ * NH), 128, ATTN_SMEM>>>(p_q, p_k, p_v, p_y);

    // 4) out = y @ w_proj : [4096,2048] @ [2048,2048]
    sgemm_kernel<<<dim3(DM / 128, (B_ * T_) / 128), 256>>>(
        p_y, w_proj, out, B_ * T_, DM, DM);
}

// round 8
// speedup vs baseline: 1.0016x; 1.0016x over previous
#include <cuda_runtime.h>
#include <math.h>

#define B_   2
#define T_   2048
#define NH   32
#define NG   8
#define HD   64
#define DM   2048     // D_MODEL
#define KVD  512      // NG*HD
#define QKVN 3072     // DM + 2*KVD

// ---------------- scratch (device globals: allocation-free) ----------------
__device__ float g_qkv[(size_t)B_ * T_ * QKVN];      // [4096, 3072]
__device__ float g_q  [(size_t)B_ * NH * T_ * HD];   // [B,H,T,D] roped
__device__ float g_k  [(size_t)B_ * NG * T_ * HD];   // [B,G,T,D] roped
__device__ float g_v  [(size_t)B_ * NG * T_ * HD];   // [B,G,T,D]
__device__ float g_y  [(size_t)B_ * T_ * DM];        // attention out, [B,T,C]

// ---------------- fp32 tiled GEMM: C[M,N] = A[M,K] @ B[K,N] ----------------
// BM=BN=128, BK=16, 256 threads, 8x8 per thread. All dims divisible.
__global__ __launch_bounds__(256) void sgemm_kernel(
    const float* __restrict__ A, const float* __restrict__ B,
    float* __restrict__ C, int M, int N, int K)
{
    __shared__ float As[16][128];   // transposed A tile
    __shared__ float Bs[16][128];

    const int tid = threadIdx.x;
    const int brow = blockIdx.y, bcol = blockIdx.x;

    const float* Ab = A + (size_t)brow * 128 * K;
    const float* Bb = B + (size_t)bcol * 128;

    const int tr = tid >> 4;       // 0..15
    const int tc = tid & 15;       // 0..15

    const int a_row  = tid >> 2;   // 0..63 (+64)
    const int a_col4 = tid & 3;    // float4 index in 16-wide row
    const int b_row  = tid >> 5;   // 0..7  (+8)
    const int b_col4 = tid & 31;   // float4 col

    float acc[8][8];
    #pragma unroll
    for (int i = 0; i < 8; i++)
        #pragma unroll
        for (int j = 0; j < 8; j++) acc[i][j] = 0.f;

    for (int k0 = 0; k0 < K; k0 += 16) {
        #pragma unroll
        for (int p = 0; p < 2; p++) {
            int r = a_row + p * 64;
            float4 v = *(const float4*)(Ab + (size_t)r * K + k0 + a_col4 * 4);
            As[a_col4 * 4 + 0][r] = v.x;
            As[a_col4 * 4 + 1][r] = v.y;
            As[a_col4 * 4 + 2][r] = v.z;
            As[a_col4 * 4 + 3][r] = v.w;
        }
        #pragma unroll
        for (int p = 0; p < 2; p++) {
            int r = b_row + p * 8;
            *(float4*)(&Bs[r][b_col4 * 4]) =
                *(const float4*)(Bb + (size_t)(k0 + r) * N + b_col4 * 4);
        }
        __syncthreads();

        #pragma unroll
        for (int kk = 0; kk < 16; kk++) {
            float a[8], b[8];
            *(float4*)(a)     = *(const float4*)(&As[kk][tr * 8]);
            *(float4*)(a + 4) = *(const float4*)(&As[kk][tr * 8 + 4]);
            *(float4*)(b)     = *(const float4*)(&Bs[kk][tc * 8]);
            *(float4*)(b + 4) = *(const float4*)(&Bs[kk][tc * 8 + 4]);
            #pragma unroll
            for (int i = 0; i < 8; i++)
                #pragma unroll
                for (int j = 0; j < 8; j++)
                    acc[i][j] = fmaf(a[i], b[j], acc[i][j]);
        }
        __syncthreads();
    }

    float* Cb = C + (size_t)brow * 128 * N + bcol * 128;
    #pragma unroll
    for (int i = 0; i < 8; i++) {
        float4 o0 = make_float4(acc[i][0], acc[i][1], acc[i][2], acc[i][3]);
        float4 o1 = make_float4(acc[i][4], acc[i][5], acc[i][6], acc[i][7]);
        float* row = Cb + (size_t)(tr * 8 + i) * N + tc * 8;
        *(float4*)(row)     = o0;
        *(float4*)(row + 4) = o1;
    }
}

// ---------------- RoPE + scatter into attention-friendly layouts ----------
// q pairs: B*T*NH*32 ; k pairs: B*T*NG*32 ; v pairs: B*T*NG*32 (copy only)
#define QP_ (B_ * T_ * NH * 32)   // 4194304
#define KP_ (B_ * T_ * NG * 32)   // 1048576

__global__ __launch_bounds__(256) void rope_prepare_kernel()
{
    int id = blockIdx.x * blockDim.x + threadIdx.x;
    if (id < QP_) {
        int i = id & 31;
        int h = (id >> 5) & 31;
        int t = (id >> 10) & 2047;
        int b = id >> 21;
        const float* src = g_qkv + ((size_t)(b * T_ + t)) * QKVN + h * 64 + 2 * i;
        float x0 = src[0], x1 = src[1];
        float inv = powf(10000.0f, -(float)(2 * i) / 64.0f);
        float sn, cs;
        sincosf((float)t * inv, &sn, &cs);
        float* dst = g_q + (((size_t)(b * NH + h)) * T_ + t) * HD + 2 * i;
        dst[0] = x0 * cs - x1 * sn;
        dst[1] = x0 * sn + x1 * cs;
    } else if (id < QP_ + KP_) {
        int id2 = id - QP_;
        int i = id2 & 31;
        int g = (id2 >> 5) & 7;
        int t = (id2 >> 8) & 2047;
        int b = id2 >> 19;
        const float* src = g_qkv + ((size_t)(b * T_ + t)) * QKVN + DM + g * 64 + 2 * i;
        float x0 = src[0], x1 = src[1];
        float inv = powf(10000.0f, -(float)(2 * i) / 64.0f);
        float sn, cs;
        sincosf((float)t * inv, &sn, &cs);
        float* dst = g_k + (((size_t)(b * NG + g)) * T_ + t) * HD + 2 * i;
        dst[0] = x0 * cs - x1 * sn;
        dst[1] = x0 * sn + x1 * cs;
    } else if (id < QP_ + 2 * KP_) {
        int id2 = id - QP_ - KP_;
        int i = id2 & 31;
        int g = (id2 >> 5) & 7;
        int t = (id2 >> 8) & 2047;
        int b = id2 >> 19;
        const float* src = g_qkv + ((size_t)(b * T_ + t)) * QKVN + DM + KVD + g * 64 + 2 * i;
        float* dst = g_v + (((size_t)(b * NG + g)) * T_ + t) * HD + 2 * i;
        dst[0] = src[0];
        dst[1] = src[1];
    }
}

// ---------------- causal flash attention, 64-row Q tiles -------------------
// grid: (T/64, B*NH), 128 threads. Each thread: 4 q-rows x 8 cols/dims.
// K/V/Q smem tiles: stride 64 with XOR chunk swizzle keyed on (row>>3)&7
// -> conflict-free K reads when 8 lanes read rows {j, j+8, ..., j+56}.
#define ATTN_SMEM ((3 * 64 * 64 + 64 * 68) * 4)   // 66560 bytes

__global__ __launch_bounds__(128) void attn_kernel(
    const float* __restrict__ Q, const float* __restrict__ K,
    const float* __restrict__ V, float* __restrict__ Y)
{
    extern __shared__ float sm[];
    float* Qs = sm;             // 64*64 swizzled
    float* Ks = sm + 4096;      // 64*64 swizzled
    float* Vs = sm + 8192;      // 64*64 swizzled
    float* Ps = sm + 12288;     // 64 rows, stride 68

    const int qt = blockIdx.x;          // 0..31
    const int bh = blockIdx.y;          // 0..63
    const int b = bh >> 5;
    const int h = bh & 31;
    const int g = h >> 2;

    const float* Qp = Q + (((size_t)(b * NH + h)) * T_ + (size_t)qt * 64) * HD;
    const float* Kp = K + (((size_t)(b * NG + g)) * T_) * HD;
    const float* Vp = V + (((size_t)(b * NG + g)) * T_) * HD;

    const int tid = threadIdx.x;

    // load Q tile (swizzled)
    for (int i = tid; i < 1024; i += 128) {
        int r = i >> 4, c = i & 15;
        int sw = c ^ ((r >> 3) & 7);
        *(float4*)(Qs + r * 64 + sw * 4) = *(const float4*)(Qp + r * 64 + c * 4);
    }

    const int r0 = (tid >> 3) << 2;     // 4 q rows
    const int c0 = (tid & 7) << 3;      // 8 k cols / 8 out dims

    float m[4], l[4], acc[4][8];
    #pragma unroll
    for (int i = 0; i < 4; i++) {
        m[i] = -1e30f; l[i] = 0.f;
        #pragma unroll
        for (int j = 0; j < 8; j++) acc[i][j] = 0.f;
    }

    const float scale = 0.125f;   // 1/sqrt(64)

    for (int kt = 0; kt <= qt; kt++) {
        __syncthreads();
        // load K,V tiles (swizzled)
        for (int i = tid; i < 1024; i += 128) {
            int r = i >> 4, c = i & 15;
            int sw = c ^ ((r >> 3) & 7);
            const size_t goff = ((size_t)kt * 64 + r) * 64 + c * 4;
            *(float4*)(Ks + r * 64 + sw * 4) = *(const float4*)(Kp + goff);
            *(float4*)(Vs + r * 64 + sw * 4) = *(const float4*)(Vp + goff);
        }
        __syncthreads();

        // ---- QK^T: s[4][8] ----
        float s[4][8];
        #pragma unroll
        for (int i = 0; i < 4; i++)
            #pragma unroll
            for (int j = 0; j < 8; j++) s[i][j] = 0.f;

        #pragma unroll
        for (int c = 0; c < 16; c++) {
            float4 qf[4], kf[8];
            #pragma unroll
            for (int i = 0; i < 4; i++) {
                int r = r0 + i;
                qf[i] = *(const float4*)(Qs + r * 64 + ((c ^ ((r >> 3) & 7)) << 2));
            }
            #pragma unroll
            for (int j = 0; j < 8; j++) {
                int r = c0 + j;
                kf[j] = *(const float4*)(Ks + r * 64 + ((c ^ ((r >> 3) & 7)) << 2));
            }
            #pragma unroll
            for (int i = 0; i < 4; i++)
                #pragma unroll
                for (int j = 0; j < 8; j++) {
                    s[i][j] = fmaf(qf[i].x, kf[j].x, s[i][j]);
                    s[i][j] = fmaf(qf[i].y, kf[j].y, s[i][j]);
                    s[i][j] = fmaf(qf[i].z, kf[j].z, s[i][j]);
                    s[i][j] = fmaf(qf[i].w, kf[j].w, s[i][j]);
                }
        }

        // ---- online softmax (8 consecutive lanes share each q row) ----
        const bool diag = (kt == qt);
        #pragma unroll
        for (int i = 0; i < 4; i++) {
            #pragma unroll
            for (int j = 0; j < 8; j++) {
                float v = s[i][j] * scale;
                if (diag && (c0 + j) > (r0 + i)) v = -1e30f;
                s[i][j] = v;
            }
            float mt = s[i][0];
            #pragma unroll
            for (int j = 1; j < 8; j++) mt = fmaxf(mt, s[i][j]);
            #pragma unroll
            for (int o = 1; o < 8; o <<= 1)
                mt = fmaxf(mt, __shfl_xor_sync(0xffffffffu, mt, o));
            float mn = fmaxf(m[i], mt);
            float corr = expf(m[i] - mn);
            float lt = 0.f;
            #pragma unroll
            for (int j = 0; j < 8; j++) {
                s[i][j] = expf(s[i][j] - mn);
                lt += s[i][j];
            }
            #pragma unroll
            for (int o = 1; o < 8; o <<= 1)
                lt += __shfl_xor_sync(0xffffffffu, lt, o);
            l[i] = l[i] * corr + lt;
            m[i] = mn;
            #pragma unroll
            for (int j = 0; j < 8; j++) acc[i][j] *= corr;

            float4 p0 = make_float4(s[i][0], s[i][1], s[i][2], s[i][3]);
            float4 p1 = make_float4(s[i][4], s[i][5], s[i][6], s[i][7]);
            *(float4*)(Ps + (r0 + i) * 68 + c0)     = p0;
            *(float4*)(Ps + (r0 + i) * 68 + c0 + 4) = p1;
        }
        __syncthreads();

        // ---- PV: acc += P @ V  (thread dims = c0..c0+7) ----
        const int cq = c0 >> 2;   // even chunk base
        #pragma unroll 8
        for (int k = 0; k < 64; k++) {
            int key = (k >> 3) & 7;
            float4 v0 = *(const float4*)(Vs + k * 64 + ((cq ^ key) << 2));
            float4 v1 = *(const float4*)(Vs + k * 64 + (((cq + 1) ^ key) << 2));
            #pragma unroll
            for (int i = 0; i < 4; i++) {
                float p = Ps[(r0 + i) * 68 + k];
                acc[i][0] = fmaf(p, v0.x, acc[i][0]);
                acc[i][1] = fmaf(p, v0.y, acc[i][1]);
                acc[i][2] = fmaf(p, v0.z, acc[i][2]);
                acc[i][3] = fmaf(p, v0.w, acc[i][3]);
                acc[i][4] = fmaf(p, v1.x, acc[i][4]);
                acc[i][5] = fmaf(p, v1.y, acc[i][5]);
                acc[i][6] = fmaf(p, v1.z, acc[i][6]);
                acc[i][7] = fmaf(p, v1.w, acc[i][7]);
            }
        }
    }

    // epilogue -> g_y in (B,T,C) layout for the proj GEMM
    #pragma unroll
    for (int i = 0; i < 4; i++) {
        float inv = 1.0f / l[i];
        float* dst = Y + ((size_t)(b * T_ + qt * 64 + r0 + i)) * DM + h * 64 + c0;
        float4 o0 = make_float4(acc[i][0] * inv, acc[i][1] * inv,
                                acc[i][2] * inv, acc[i][3] * inv);
        float4 o1 = make_float4(acc[i][4] * inv, acc[i][5] * inv,
                                acc[i][6] * inv, acc[i][7] * inv);
        *(float4*)(dst)     = o0;
        *(float4*)(dst + 4) = o1;
    }
}

// ---------------- launch ---------------------------------------------------
extern "C" void kernel_launch(void* const* d_in, const int* in_sizes, int n_in,
                              void* d_out, int out_size)
{
    const float* x      = (const float*)d_in[0];
    const float* w_qkv  = (const float*)d_in[1];
    const float* w_proj = (const float*)d_in[2];
    float* out = (float*)d_out;

    float *p_qkv, *p_q, *p_k, *p_v, *p_y;
    cudaGetSymbolAddress((void**)&p_qkv, g_qkv);
    cudaGetSymbolAddress((void**)&p_q,   g_q);
    cudaGetSymbolAddress((void**)&p_k,   g_k);
    cudaGetSymbolAddress((void**)&p_v,   g_v);
    cudaGetSymbolAddress((void**)&p_y,   g_y);

    cudaFuncSetAttribute(attn_kernel,
        cudaFuncAttributeMaxDynamicSharedMemorySize, ATTN_SMEM);

    // 1) qkv = x @ w_qkv : [4096,2048] @ [2048,3072]
    sgemm_kernel<<<dim3(QKVN / 128, (B_ * T_) / 128), 256>>>(
        x, w_qkv, p_qkv, B_ * T_, QKVN, DM);

    // 2) RoPE + scatter to [B,H,T,D] / [B,G,T,D]
    {
        int total = QP_ + 2 * KP_;
        rope_prepare_kernel<<<(total + 255) / 256, 256>>>();
    }

    // 3) causal GQA flash attention -> g_y [B,T,C]
    attn_kernel<<<dim3(T_ / 64, B_ * NH), 128, ATTN_SMEM>>>(p_q, p_k, p_v, p_y);

    // 4) out = y @ w_proj : [4096,2048] @ [2048,2048]
    sgemm_kernel<<<dim3(DM / 128, (B_ * T_) / 128), 256>>>(
        p_y, w_proj, out, B_ * T_, DM, DM);
}